// round 2
// baseline (speedup 1.0000x reference)
#include <cuda_runtime.h>
#include <stdint.h>

#define N_RAYS   1048576
#define N_LEVELS 6
#define HASHMAP_SIZE (1u << 19)
#define HASH_MASK    (HASHMAP_SIZE - 1u)
#define SPHERE_R 500.0f
#define BIN_RES  64
#define NBINS    (BIN_RES * BIN_RES * BIN_RES)

// per-level scale = 16*2^L - 1 (PER_LEVEL_SCALE is exactly 2.0 in double)
__device__ __constant__ float d_scales[N_LEVELS] = {15.f, 31.f, 63.f, 127.f, 255.f, 511.f};

// scratch (fixed problem size; device globals per harness rules)
__device__ uint32_t d_hist[NBINS];
__device__ uint32_t d_offsets[NBINS];
__device__ float4   d_coords[N_RAYS];   // (cx,cy,cz, bin-as-float-bits)
__device__ float4   d_sorted[N_RAYS];   // (cx,cy,cz, origIdx-as-float-bits)

// ---------------------------------------------------------------- K0: zero hist
__global__ void k0_zero()
{
    int i = blockIdx.x * blockDim.x + threadIdx.x;
    if (i < NBINS) d_hist[i] = 0u;
}

// ---------------------------------------------------------------- shared coord math
__device__ __forceinline__ float3 ray_coords(const float* __restrict__ dirs,
                                             const float* __restrict__ origs, int i)
{
    const float dx = dirs[3 * i + 0], dy = dirs[3 * i + 1], dz = dirs[3 * i + 2];
    const float ox = origs[3 * i + 0], oy = origs[3 * i + 1], oz = origs[3 * i + 2];
    float b    = 2.0f * (ox * dx + oy * dy + oz * dz);
    float c    = (ox * ox + oy * oy + oz * oz) - SPHERE_R * SPHERE_R;
    float disc = b * b - 4.0f * c;
    float t    = 0.5f * (sqrtf(fmaxf(disc, 0.0f)) - b);
    const float inv2R = 1.0f / (2.0f * SPHERE_R);
    float3 r;
    r.x = fminf(fmaxf((ox + t * dx + SPHERE_R) * inv2R, 0.0f), 1.0f);
    r.y = fminf(fmaxf((oy + t * dy + SPHERE_R) * inv2R, 0.0f), 1.0f);
    r.z = fminf(fmaxf((oz + t * dz + SPHERE_R) * inv2R, 0.0f), 1.0f);
    return r;
}

// ---------------------------------------------------------------- K1: coords + histogram
__global__ void __launch_bounds__(256)
k1_bin(const float* __restrict__ dirs, const float* __restrict__ origs, int n)
{
    int i = blockIdx.x * blockDim.x + threadIdx.x;
    if (i >= n) return;
    float3 cc = ray_coords(dirs, origs, i);
    uint32_t bx = min((uint32_t)(cc.x * BIN_RES), (uint32_t)(BIN_RES - 1));
    uint32_t by = min((uint32_t)(cc.y * BIN_RES), (uint32_t)(BIN_RES - 1));
    uint32_t bz = min((uint32_t)(cc.z * BIN_RES), (uint32_t)(BIN_RES - 1));
    uint32_t bin = bx | (by << 6) | (bz << 12);
    d_coords[i] = make_float4(cc.x, cc.y, cc.z, __uint_as_float(bin));
    atomicAdd(&d_hist[bin], 1u);
}

// ---------------------------------------------------------------- K2: exclusive scan (single block)
__global__ void __launch_bounds__(1024)
k2_scan()
{
    __shared__ uint32_t wsum[32];
    __shared__ uint32_t wpre[32];
    __shared__ uint32_t carry;
    __shared__ uint32_t total;
    const int tid = threadIdx.x, lane = tid & 31, wid = tid >> 5;
    if (tid == 0) carry = 0u;
    __syncthreads();

    for (int base = 0; base < NBINS; base += 1024) {
        uint32_t v = d_hist[base + tid];
        uint32_t x = v;
#pragma unroll
        for (int d = 1; d < 32; d <<= 1) {
            uint32_t y = __shfl_up_sync(0xffffffffu, x, d);
            if (lane >= d) x += y;
        }
        if (lane == 31) wsum[wid] = x;
        __syncthreads();
        if (wid == 0) {
            uint32_t s = wsum[lane];
            uint32_t t = s;
#pragma unroll
            for (int d = 1; d < 32; d <<= 1) {
                uint32_t y = __shfl_up_sync(0xffffffffu, t, d);
                if (lane >= d) t += y;
            }
            wpre[lane] = t - s;            // exclusive prefix of warp sums
            if (lane == 31) total = t;     // block total this chunk
        }
        __syncthreads();
        d_offsets[base + tid] = carry + wpre[wid] + (x - v);
        __syncthreads();
        if (tid == 0) carry += total;
        __syncthreads();
    }
}

// ---------------------------------------------------------------- K3: scatter into sorted order
__global__ void __launch_bounds__(256)
k3_scatter(int n)
{
    int i = blockIdx.x * blockDim.x + threadIdx.x;
    if (i >= n) return;
    float4 c = d_coords[i];
    uint32_t bin = __float_as_uint(c.w);
    uint32_t pos = atomicAdd(&d_offsets[bin], 1u);
    c.w = __uint_as_float((uint32_t)i);
    d_sorted[pos] = c;
}

// ---------------------------------------------------------------- K4: coherent encode
__global__ void __launch_bounds__(256)
k4_encode(const float* __restrict__ table, float4* __restrict__ out, int n)
{
    int j = blockIdx.x * blockDim.x + threadIdx.x;
    if (j >= n) return;
    float4 c = d_sorted[j];
    const float cx = c.x, cy = c.y, cz = c.z;
    const uint32_t orig = __float_as_uint(c.w);

    float4* orow = out + (size_t)orig * 6;

#pragma unroll
    for (int L = 0; L < N_LEVELS; ++L) {
        const float scale = d_scales[L];
        float px = cx * scale + 0.5f;
        float py = cy * scale + 0.5f;
        float pz = cz * scale + 0.5f;
        float fx = floorf(px), fy = floorf(py), fz = floorf(pz);
        float wx = px - fx, wy = py - fy, wz = pz - fz;
        uint32_t gx = (uint32_t)fx, gy = (uint32_t)fy, gz = (uint32_t)fz;

        uint32_t i000, i100, i010, i110, i001, i101, i011, i111;
        if (L < 3) {
            const uint32_t r  = 16u << L;
            const uint32_t rm = r - 1u;
            uint32_t x0 = min(gx, rm),           x1 = min(gx + 1u, rm);
            uint32_t y0 = min(gy, rm) * r,       y1 = min(gy + 1u, rm) * r;
            uint32_t z0 = min(gz, rm) * r * r,   z1 = min(gz + 1u, rm) * r * r;
            i000 = x0 + y0 + z0; i100 = x1 + y0 + z0;
            i010 = x0 + y1 + z0; i110 = x1 + y1 + z0;
            i001 = x0 + y0 + z1; i101 = x1 + y0 + z1;
            i011 = x0 + y1 + z1; i111 = x1 + y1 + z1;
        } else {
            uint32_t hx0 = gx,               hx1 = gx + 1u;
            uint32_t hy0 = gy * 2654435761u, hy1 = (gy + 1u) * 2654435761u;
            uint32_t hz0 = gz * 805459861u,  hz1 = (gz + 1u) * 805459861u;
            i000 = (hx0 ^ hy0 ^ hz0) & HASH_MASK; i100 = (hx1 ^ hy0 ^ hz0) & HASH_MASK;
            i010 = (hx0 ^ hy1 ^ hz0) & HASH_MASK; i110 = (hx1 ^ hy1 ^ hz0) & HASH_MASK;
            i001 = (hx0 ^ hy0 ^ hz1) & HASH_MASK; i101 = (hx1 ^ hy0 ^ hz1) & HASH_MASK;
            i011 = (hx0 ^ hy1 ^ hz1) & HASH_MASK; i111 = (hx1 ^ hy1 ^ hz1) & HASH_MASK;
        }

        const float4* tab = reinterpret_cast<const float4*>(table) + (size_t)L * HASHMAP_SIZE;
        float4 f000 = __ldg(tab + i000);
        float4 f100 = __ldg(tab + i100);
        float4 f010 = __ldg(tab + i010);
        float4 f110 = __ldg(tab + i110);
        float4 f001 = __ldg(tab + i001);
        float4 f101 = __ldg(tab + i101);
        float4 f011 = __ldg(tab + i011);
        float4 f111 = __ldg(tab + i111);

        float ux = 1.0f - wx, uy = 1.0f - wy, uz = 1.0f - wz;
        float w000 = ux * uy * uz, w100 = wx * uy * uz;
        float w010 = ux * wy * uz, w110 = wx * wy * uz;
        float w001 = ux * uy * wz, w101 = wx * uy * wz;
        float w011 = ux * wy * wz, w111 = wx * wy * wz;

        float4 acc;
        acc.x = f000.x * w000 + f100.x * w100 + f010.x * w010 + f110.x * w110
              + f001.x * w001 + f101.x * w101 + f011.x * w011 + f111.x * w111;
        acc.y = f000.y * w000 + f100.y * w100 + f010.y * w010 + f110.y * w110
              + f001.y * w001 + f101.y * w101 + f011.y * w011 + f111.y * w111;
        acc.z = f000.z * w000 + f100.z * w100 + f010.z * w010 + f110.z * w110
              + f001.z * w001 + f101.z * w101 + f011.z * w011 + f111.z * w111;
        acc.w = f000.w * w000 + f100.w * w100 + f010.w * w010 + f110.w * w110
              + f001.w * w001 + f101.w * w101 + f011.w * w011 + f111.w * w111;

        orow[L] = acc;
    }
}

// ---------------------------------------------------------------- launch
extern "C" void kernel_launch(void* const* d_in, const int* in_sizes, int n_in,
                              void* d_out, int out_size)
{
    const float* view_dirs   = (const float*)d_in[0];
    const float* ray_origins = (const float*)d_in[1];
    const float* table       = (const float*)d_in[2];
    float4* out              = (float4*)d_out;

    int n = in_sizes[0] / 3;
    int threads = 256;
    int blocks  = (n + threads - 1) / threads;

    k0_zero<<<(NBINS + 255) / 256, 256>>>();
    k1_bin<<<blocks, threads>>>(view_dirs, ray_origins, n);
    k2_scan<<<1, 1024>>>();
    k3_scatter<<<blocks, threads>>>(n);
    k4_encode<<<blocks, threads>>>(table, out, n);
}

// round 4
// speedup vs baseline: 2.5824x; 2.5824x over previous
#include <cuda_runtime.h>
#include <stdint.h>

#define N_RAYS   1048576
#define N_LEVELS 6
#define HASHMAP_SIZE (1u << 19)
#define HASH_MASK    (HASHMAP_SIZE - 1u)
#define SPHERE_R 500.0f

#define BIN_RES   128
#define BIN_BITS  7
#define NBINS     (1u << (3 * BIN_BITS))      // 2097152
#define SCAN_CHUNK 2048
#define SCAN_BLOCKS (NBINS / SCAN_CHUNK)      // 1024

__device__ __constant__ float d_scales[N_LEVELS] = {15.f, 31.f, 63.f, 127.f, 255.f, 511.f};

// scratch (device globals; fixed problem size)
__device__ uint32_t d_hist[NBINS];
__device__ uint32_t d_offsets[NBINS];
__device__ uint32_t d_bsum[SCAN_BLOCKS];
__device__ float4   d_coords[N_RAYS];
__device__ uint32_t d_bin[N_RAYS];
__device__ uint32_t d_perm[N_RAYS];

// ---------------------------------------------------------------- helpers
__device__ __forceinline__ uint32_t expand3(uint32_t v)
{
    v = (v | (v << 16)) & 0x030000FFu;
    v = (v | (v << 8))  & 0x0300F00Fu;
    v = (v | (v << 4))  & 0x030C30C3u;
    v = (v | (v << 2))  & 0x09249249u;
    return v;
}

__device__ __forceinline__ float3 ray_coords(const float* __restrict__ dirs,
                                             const float* __restrict__ origs, int i)
{
    const float dx = dirs[3 * i + 0], dy = dirs[3 * i + 1], dz = dirs[3 * i + 2];
    const float ox = origs[3 * i + 0], oy = origs[3 * i + 1], oz = origs[3 * i + 2];
    float b    = 2.0f * (ox * dx + oy * dy + oz * dz);
    float c    = (ox * ox + oy * oy + oz * oz) - SPHERE_R * SPHERE_R;
    float disc = b * b - 4.0f * c;
    float t    = 0.5f * (sqrtf(fmaxf(disc, 0.0f)) - b);
    const float inv2R = 1.0f / (2.0f * SPHERE_R);
    float3 r;
    r.x = fminf(fmaxf((ox + t * dx + SPHERE_R) * inv2R, 0.0f), 1.0f);
    r.y = fminf(fmaxf((oy + t * dy + SPHERE_R) * inv2R, 0.0f), 1.0f);
    r.z = fminf(fmaxf((oz + t * dz + SPHERE_R) * inv2R, 0.0f), 1.0f);
    return r;
}

// ---------------------------------------------------------------- K0: zero hist (uint4)
__global__ void k0_zero()
{
    int i = blockIdx.x * blockDim.x + threadIdx.x;
    reinterpret_cast<uint4*>(d_hist)[i] = make_uint4(0u, 0u, 0u, 0u);
}

// ---------------------------------------------------------------- K1: coords + Morton bin + histogram
__global__ void __launch_bounds__(256)
k1_bin(const float* __restrict__ dirs, const float* __restrict__ origs, int n)
{
    int i = blockIdx.x * blockDim.x + threadIdx.x;
    if (i >= n) return;
    float3 cc = ray_coords(dirs, origs, i);
    uint32_t bx = min((uint32_t)(cc.x * BIN_RES), (uint32_t)(BIN_RES - 1));
    uint32_t by = min((uint32_t)(cc.y * BIN_RES), (uint32_t)(BIN_RES - 1));
    uint32_t bz = min((uint32_t)(cc.z * BIN_RES), (uint32_t)(BIN_RES - 1));
    uint32_t bin = expand3(bx) | (expand3(by) << 1) | (expand3(bz) << 2);
    d_coords[i] = make_float4(cc.x, cc.y, cc.z, 0.0f);
    d_bin[i] = bin;
    atomicAdd(&d_hist[bin], 1u);
}

// ---------------------------------------------------------------- block scan helper (1024 threads)
__device__ __forceinline__ uint32_t block_incl_scan_1024(uint32_t v, uint32_t* wsum)
{
    const int lane = threadIdx.x & 31, wid = threadIdx.x >> 5;
    uint32_t x = v;
#pragma unroll
    for (int d = 1; d < 32; d <<= 1) {
        uint32_t y = __shfl_up_sync(0xffffffffu, x, d);
        if (lane >= d) x += y;
    }
    if (lane == 31) wsum[wid] = x;
    __syncthreads();
    if (wid == 0) {
        uint32_t s = wsum[lane];
        uint32_t t = s;
#pragma unroll
        for (int d = 1; d < 32; d <<= 1) {
            uint32_t y = __shfl_up_sync(0xffffffffu, t, d);
            if (lane >= d) t += y;
        }
        wsum[lane] = t - s;
    }
    __syncthreads();
    return x + wsum[wid];
}

// ---------------------------------------------------------------- K2a: per-chunk scan (2048 elems/block)
__global__ void __launch_bounds__(1024)
k2a_scan()
{
    __shared__ uint32_t wsum[32];
    const int base = blockIdx.x * SCAN_CHUNK;
    const int t = threadIdx.x;
    uint2 e = reinterpret_cast<const uint2*>(d_hist + base)[t];
    uint32_t s = e.x + e.y;
    uint32_t incl = block_incl_scan_1024(s, wsum);
    uint32_t excl = incl - s;
    reinterpret_cast<uint2*>(d_offsets + base)[t] = make_uint2(excl, excl + e.x);
    if (t == 1023) d_bsum[blockIdx.x] = incl;
}

// ---------------------------------------------------------------- K2b: scan of block sums
__global__ void __launch_bounds__(1024)
k2b_scan()
{
    __shared__ uint32_t wsum[32];
    const int t = threadIdx.x;
    uint32_t v = d_bsum[t];
    uint32_t incl = block_incl_scan_1024(v, wsum);
    d_bsum[t] = incl - v;
}

// ---------------------------------------------------------------- K2c: uniform add
__global__ void __launch_bounds__(1024)
k2c_add()
{
    const int base = blockIdx.x * SCAN_CHUNK;
    const int t = threadIdx.x;
    uint32_t add = d_bsum[blockIdx.x];
    uint2 e = reinterpret_cast<uint2*>(d_offsets + base)[t];
    e.x += add; e.y += add;
    reinterpret_cast<uint2*>(d_offsets + base)[t] = e;
}

// ---------------------------------------------------------------- K3: build permutation
__global__ void __launch_bounds__(256)
k3_scatter(int n)
{
    int i = blockIdx.x * blockDim.x + threadIdx.x;
    if (i >= n) return;
    uint32_t bin = d_bin[i];
    uint32_t pos = atomicAdd(&d_offsets[bin], 1u);
    d_perm[pos] = (uint32_t)i;
}

// ---------------------------------------------------------------- K4: coherent encode, warp-coop stores
__global__ void __launch_bounds__(256)
k4_encode(const float* __restrict__ table, float4* __restrict__ out, int n)
{
    __shared__ float sbuf[8][32][28];   // 8 warps x 32 rows x 96B (stride 112B, 16B-aligned)

    int j = blockIdx.x * blockDim.x + threadIdx.x;
    const int lane = threadIdx.x & 31;
    const int w    = threadIdx.x >> 5;
    bool active = (j < n);

    uint32_t orig = 0;
    float cx = 0.f, cy = 0.f, cz = 0.f;
    if (active) {
        orig = d_perm[j];
        float4 c = d_coords[orig];
        cx = c.x; cy = c.y; cz = c.z;
    }

#pragma unroll
    for (int L = 0; L < N_LEVELS; ++L) {
        const float scale = d_scales[L];
        float px = cx * scale + 0.5f;
        float py = cy * scale + 0.5f;
        float pz = cz * scale + 0.5f;
        float fx = floorf(px), fy = floorf(py), fz = floorf(pz);
        float wx = px - fx, wy = py - fy, wz = pz - fz;
        uint32_t gx = (uint32_t)fx, gy = (uint32_t)fy, gz = (uint32_t)fz;

        uint32_t i000, i100, i010, i110, i001, i101, i011, i111;
        if (L < 3) {
            const uint32_t r  = 16u << L;
            const uint32_t rm = r - 1u;
            uint32_t x0 = min(gx, rm),           x1 = min(gx + 1u, rm);
            uint32_t y0 = min(gy, rm) * r,       y1 = min(gy + 1u, rm) * r;
            uint32_t z0 = min(gz, rm) * r * r,   z1 = min(gz + 1u, rm) * r * r;
            i000 = x0 + y0 + z0; i100 = x1 + y0 + z0;
            i010 = x0 + y1 + z0; i110 = x1 + y1 + z0;
            i001 = x0 + y0 + z1; i101 = x1 + y0 + z1;
            i011 = x0 + y1 + z1; i111 = x1 + y1 + z1;
        } else {
            uint32_t hx0 = gx,               hx1 = gx + 1u;
            uint32_t hy0 = gy * 2654435761u, hy1 = (gy + 1u) * 2654435761u;
            uint32_t hz0 = gz * 805459861u,  hz1 = (gz + 1u) * 805459861u;
            i000 = (hx0 ^ hy0 ^ hz0) & HASH_MASK; i100 = (hx1 ^ hy0 ^ hz0) & HASH_MASK;
            i010 = (hx0 ^ hy1 ^ hz0) & HASH_MASK; i110 = (hx1 ^ hy1 ^ hz0) & HASH_MASK;
            i001 = (hx0 ^ hy0 ^ hz1) & HASH_MASK; i101 = (hx1 ^ hy0 ^ hz1) & HASH_MASK;
            i011 = (hx0 ^ hy1 ^ hz1) & HASH_MASK; i111 = (hx1 ^ hy1 ^ hz1) & HASH_MASK;
        }

        const float4* tab = reinterpret_cast<const float4*>(table) + (size_t)L * HASHMAP_SIZE;
        float4 f000, f100, f010, f110, f001, f101, f011, f111;
        if (active) {
            f000 = __ldg(tab + i000);
            f100 = __ldg(tab + i100);
            f010 = __ldg(tab + i010);
            f110 = __ldg(tab + i110);
            f001 = __ldg(tab + i001);
            f101 = __ldg(tab + i101);
            f011 = __ldg(tab + i011);
            f111 = __ldg(tab + i111);
        } else {
            f000 = f100 = f010 = f110 = f001 = f101 = f011 = f111 = make_float4(0.f, 0.f, 0.f, 0.f);
        }

        float ux = 1.0f - wx, uy = 1.0f - wy, uz = 1.0f - wz;
        float w000 = ux * uy * uz, w100 = wx * uy * uz;
        float w010 = ux * wy * uz, w110 = wx * wy * uz;
        float w001 = ux * uy * wz, w101 = wx * uy * wz;
        float w011 = ux * wy * wz, w111 = wx * wy * wz;

        float4 acc;
        acc.x = f000.x * w000 + f100.x * w100 + f010.x * w010 + f110.x * w110
              + f001.x * w001 + f101.x * w101 + f011.x * w011 + f111.x * w111;
        acc.y = f000.y * w000 + f100.y * w100 + f010.y * w010 + f110.y * w110
              + f001.y * w001 + f101.y * w101 + f011.y * w011 + f111.y * w111;
        acc.z = f000.z * w000 + f100.z * w100 + f010.z * w010 + f110.z * w110
              + f001.z * w001 + f101.z * w101 + f011.z * w011 + f111.z * w111;
        acc.w = f000.w * w000 + f100.w * w100 + f010.w * w010 + f110.w * w110
              + f001.w * w001 + f101.w * w101 + f011.w * w011 + f111.w * w111;

        *reinterpret_cast<float4*>(&sbuf[w][lane][L * 4]) = acc;
    }

    __syncwarp();

    const unsigned fullmask = 0xffffffffu;
    unsigned m = __ballot_sync(fullmask, active);
    bool warp_full = (m == 0xffffffffu);

    if (warp_full) {
        // warp-cooperative scatter; every lane executes the shfl (uniform),
        // only the store is predicated.
#pragma unroll
        for (int it = 0; it < 7; ++it) {
            int f  = it * 30 + lane;
            int fc = f < 192 ? f : 191;          // clamp for uniform execution
            int r  = fc / 6;
            int L  = fc - r * 6;
            float4 v = *reinterpret_cast<float4*>(&sbuf[w][r][L * 4]);
            uint32_t org_r = __shfl_sync(fullmask, orig, r);
            if (lane < 30 && f < 192)
                out[(size_t)org_r * 6 + L] = v;
        }
    } else if (active) {
        float4* orow = out + (size_t)orig * 6;
#pragma unroll
        for (int L = 0; L < N_LEVELS; ++L)
            orow[L] = *reinterpret_cast<float4*>(&sbuf[w][lane][L * 4]);
    }
}

// ---------------------------------------------------------------- launch
extern "C" void kernel_launch(void* const* d_in, const int* in_sizes, int n_in,
                              void* d_out, int out_size)
{
    const float* view_dirs   = (const float*)d_in[0];
    const float* ray_origins = (const float*)d_in[1];
    const float* table       = (const float*)d_in[2];
    float4* out              = (float4*)d_out;

    int n = in_sizes[0] / 3;
    int threads = 256;
    int blocks  = (n + threads - 1) / threads;

    k0_zero<<<NBINS / 4 / 256, 256>>>();
    k1_bin<<<blocks, threads>>>(view_dirs, ray_origins, n);
    k2a_scan<<<SCAN_BLOCKS, 1024>>>();
    k2b_scan<<<1, 1024>>>();
    k2c_add<<<SCAN_BLOCKS, 1024>>>();
    k3_scatter<<<blocks, threads>>>(n);
    k4_encode<<<blocks, threads>>>(table, out, n);
}

// round 5
// speedup vs baseline: 2.6440x; 1.0238x over previous
#include <cuda_runtime.h>
#include <stdint.h>

#define N_RAYS   1048576
#define N_LEVELS 6
#define HASHMAP_SIZE (1u << 19)
#define HASH_MASK    (HASHMAP_SIZE - 1u)
#define SPHERE_R 500.0f

#define BIN_RES   128
#define NBINS     (1u << 21)                  // 128^3 Morton bins
#define SCAN_CHUNK 2048
#define SCAN_BLOCKS (NBINS / SCAN_CHUNK)      // 1024

__device__ __constant__ float d_scales[N_LEVELS] = {15.f, 31.f, 63.f, 127.f, 255.f, 511.f};

__device__ uint32_t d_hist[NBINS];
__device__ uint32_t d_offsets[NBINS];   // chunk-local after k2a
__device__ uint32_t d_bsum[SCAN_BLOCKS];
__device__ float4   d_coords[N_RAYS];
__device__ uint32_t d_bin[N_RAYS];
__device__ uint32_t d_perm[N_RAYS];

// ---------------------------------------------------------------- helpers
__device__ __forceinline__ uint32_t expand3(uint32_t v)
{
    v = (v | (v << 16)) & 0x030000FFu;
    v = (v | (v << 8))  & 0x0300F00Fu;
    v = (v | (v << 4))  & 0x030C30C3u;
    v = (v | (v << 2))  & 0x09249249u;
    return v;
}

__device__ __forceinline__ float3 ray_coords(const float* __restrict__ dirs,
                                             const float* __restrict__ origs, int i)
{
    const float dx = dirs[3 * i + 0], dy = dirs[3 * i + 1], dz = dirs[3 * i + 2];
    const float ox = origs[3 * i + 0], oy = origs[3 * i + 1], oz = origs[3 * i + 2];
    float b    = 2.0f * (ox * dx + oy * dy + oz * dz);
    float c    = (ox * ox + oy * oy + oz * oz) - SPHERE_R * SPHERE_R;
    float disc = b * b - 4.0f * c;
    float t    = 0.5f * (sqrtf(fmaxf(disc, 0.0f)) - b);
    const float inv2R = 1.0f / (2.0f * SPHERE_R);
    float3 r;
    r.x = fminf(fmaxf((ox + t * dx + SPHERE_R) * inv2R, 0.0f), 1.0f);
    r.y = fminf(fmaxf((oy + t * dy + SPHERE_R) * inv2R, 0.0f), 1.0f);
    r.z = fminf(fmaxf((oz + t * dz + SPHERE_R) * inv2R, 0.0f), 1.0f);
    return r;
}

__device__ __forceinline__ void stcs_f4(float4* p, float4 v)
{
    asm volatile("st.global.cs.v4.f32 [%0], {%1,%2,%3,%4};"
                 :: "l"(p), "f"(v.x), "f"(v.y), "f"(v.z), "f"(v.w) : "memory");
}
__device__ __forceinline__ void stcs_u32(uint32_t* p, uint32_t v)
{
    asm volatile("st.global.cs.u32 [%0], %1;" :: "l"(p), "r"(v) : "memory");
}
__device__ __forceinline__ float4 ldcs_f4(const float4* p)
{
    float4 v;
    asm volatile("ld.global.cs.v4.f32 {%0,%1,%2,%3}, [%4];"
                 : "=f"(v.x), "=f"(v.y), "=f"(v.z), "=f"(v.w) : "l"(p));
    return v;
}

// ---------------------------------------------------------------- K0: zero hist
__global__ void k0_zero()
{
    int i = blockIdx.x * blockDim.x + threadIdx.x;
    reinterpret_cast<uint4*>(d_hist)[i] = make_uint4(0u, 0u, 0u, 0u);
}

// ---------------------------------------------------------------- K1: coords + Morton bin + histogram
__global__ void __launch_bounds__(256)
k1_bin(const float* __restrict__ dirs, const float* __restrict__ origs, int n)
{
    int i = blockIdx.x * blockDim.x + threadIdx.x;
    if (i >= n) return;
    float3 cc = ray_coords(dirs, origs, i);
    uint32_t bx = min((uint32_t)(cc.x * BIN_RES), (uint32_t)(BIN_RES - 1));
    uint32_t by = min((uint32_t)(cc.y * BIN_RES), (uint32_t)(BIN_RES - 1));
    uint32_t bz = min((uint32_t)(cc.z * BIN_RES), (uint32_t)(BIN_RES - 1));
    uint32_t bin = expand3(bx) | (expand3(by) << 1) | (expand3(bz) << 2);
    stcs_f4(&d_coords[i], make_float4(cc.x, cc.y, cc.z, 0.0f));
    stcs_u32(&d_bin[i], bin);
    atomicAdd(&d_hist[bin], 1u);
}

// ---------------------------------------------------------------- block scan helper
__device__ __forceinline__ uint32_t block_incl_scan_1024(uint32_t v, uint32_t* wsum)
{
    const int lane = threadIdx.x & 31, wid = threadIdx.x >> 5;
    uint32_t x = v;
#pragma unroll
    for (int d = 1; d < 32; d <<= 1) {
        uint32_t y = __shfl_up_sync(0xffffffffu, x, d);
        if (lane >= d) x += y;
    }
    if (lane == 31) wsum[wid] = x;
    __syncthreads();
    if (wid == 0) {
        uint32_t s = wsum[lane];
        uint32_t t = s;
#pragma unroll
        for (int d = 1; d < 32; d <<= 1) {
            uint32_t y = __shfl_up_sync(0xffffffffu, t, d);
            if (lane >= d) t += y;
        }
        wsum[lane] = t - s;
    }
    __syncthreads();
    return x + wsum[wid];
}

// ---------------------------------------------------------------- K2a: per-chunk scan (chunk-local offsets)
__global__ void __launch_bounds__(1024)
k2a_scan()
{
    __shared__ uint32_t wsum[32];
    const int base = blockIdx.x * SCAN_CHUNK;
    const int t = threadIdx.x;
    uint2 e = reinterpret_cast<const uint2*>(d_hist + base)[t];
    uint32_t s = e.x + e.y;
    uint32_t incl = block_incl_scan_1024(s, wsum);
    uint32_t excl = incl - s;
    reinterpret_cast<uint2*>(d_offsets + base)[t] = make_uint2(excl, excl + e.x);
    if (t == 1023) d_bsum[blockIdx.x] = incl;
}

// ---------------------------------------------------------------- K2b: exclusive scan of chunk sums
__global__ void __launch_bounds__(1024)
k2b_scan()
{
    __shared__ uint32_t wsum[32];
    const int t = threadIdx.x;
    uint32_t v = d_bsum[t];
    uint32_t incl = block_incl_scan_1024(v, wsum);
    d_bsum[t] = incl - v;
}

// ---------------------------------------------------------------- K3: build permutation (adds chunk base here)
__global__ void __launch_bounds__(256)
k3_scatter(int n)
{
    int i = blockIdx.x * blockDim.x + threadIdx.x;
    if (i >= n) return;
    uint32_t bin  = d_bin[i];
    uint32_t pos  = atomicAdd(&d_offsets[bin], 1u) + __ldg(&d_bsum[bin / SCAN_CHUNK]);
    stcs_u32(&d_perm[pos], (uint32_t)i);
}

// ---------------------------------------------------------------- K4: coherent encode, warp-coop streaming stores
__global__ void __launch_bounds__(256)
k4_encode(const float* __restrict__ table, float4* __restrict__ out, int n)
{
    __shared__ float sbuf[8][32][28];   // 8 warps x 32 rows x 96B (stride 112B)

    int j = blockIdx.x * blockDim.x + threadIdx.x;
    const int lane = threadIdx.x & 31;
    const int w    = threadIdx.x >> 5;
    bool active = (j < n);

    uint32_t orig = 0;
    float cx = 0.f, cy = 0.f, cz = 0.f;
    if (active) {
        orig = d_perm[j];
        float4 c = ldcs_f4(&d_coords[orig]);
        cx = c.x; cy = c.y; cz = c.z;
    }

#pragma unroll
    for (int L = 0; L < N_LEVELS; ++L) {
        const float scale = d_scales[L];
        float px = cx * scale + 0.5f;
        float py = cy * scale + 0.5f;
        float pz = cz * scale + 0.5f;
        float fx = floorf(px), fy = floorf(py), fz = floorf(pz);
        float wx = px - fx, wy = py - fy, wz = pz - fz;
        uint32_t gx = (uint32_t)fx, gy = (uint32_t)fy, gz = (uint32_t)fz;

        uint32_t i000, i100, i010, i110, i001, i101, i011, i111;
        if (L < 3) {
            const uint32_t r  = 16u << L;
            const uint32_t rm = r - 1u;
            uint32_t x0 = min(gx, rm),           x1 = min(gx + 1u, rm);
            uint32_t y0 = min(gy, rm) * r,       y1 = min(gy + 1u, rm) * r;
            uint32_t z0 = min(gz, rm) * r * r,   z1 = min(gz + 1u, rm) * r * r;
            i000 = x0 + y0 + z0; i100 = x1 + y0 + z0;
            i010 = x0 + y1 + z0; i110 = x1 + y1 + z0;
            i001 = x0 + y0 + z1; i101 = x1 + y0 + z1;
            i011 = x0 + y1 + z1; i111 = x1 + y1 + z1;
        } else {
            uint32_t hx0 = gx,               hx1 = gx + 1u;
            uint32_t hy0 = gy * 2654435761u, hy1 = (gy + 1u) * 2654435761u;
            uint32_t hz0 = gz * 805459861u,  hz1 = (gz + 1u) * 805459861u;
            i000 = (hx0 ^ hy0 ^ hz0) & HASH_MASK; i100 = (hx1 ^ hy0 ^ hz0) & HASH_MASK;
            i010 = (hx0 ^ hy1 ^ hz0) & HASH_MASK; i110 = (hx1 ^ hy1 ^ hz0) & HASH_MASK;
            i001 = (hx0 ^ hy0 ^ hz1) & HASH_MASK; i101 = (hx1 ^ hy0 ^ hz1) & HASH_MASK;
            i011 = (hx0 ^ hy1 ^ hz1) & HASH_MASK; i111 = (hx1 ^ hy1 ^ hz1) & HASH_MASK;
        }

        const float4* tab = reinterpret_cast<const float4*>(table) + (size_t)L * HASHMAP_SIZE;
        float4 f000, f100, f010, f110, f001, f101, f011, f111;
        if (active) {
            f000 = __ldg(tab + i000);
            f100 = __ldg(tab + i100);
            f010 = __ldg(tab + i010);
            f110 = __ldg(tab + i110);
            f001 = __ldg(tab + i001);
            f101 = __ldg(tab + i101);
            f011 = __ldg(tab + i011);
            f111 = __ldg(tab + i111);
        } else {
            f000 = f100 = f010 = f110 = f001 = f101 = f011 = f111 = make_float4(0.f, 0.f, 0.f, 0.f);
        }

        float ux = 1.0f - wx, uy = 1.0f - wy, uz = 1.0f - wz;
        float w000 = ux * uy * uz, w100 = wx * uy * uz;
        float w010 = ux * wy * uz, w110 = wx * wy * uz;
        float w001 = ux * uy * wz, w101 = wx * uy * wz;
        float w011 = ux * wy * wz, w111 = wx * wy * wz;

        float4 acc;
        acc.x = f000.x * w000 + f100.x * w100 + f010.x * w010 + f110.x * w110
              + f001.x * w001 + f101.x * w101 + f011.x * w011 + f111.x * w111;
        acc.y = f000.y * w000 + f100.y * w100 + f010.y * w010 + f110.y * w110
              + f001.y * w001 + f101.y * w101 + f011.y * w011 + f111.y * w111;
        acc.z = f000.z * w000 + f100.z * w100 + f010.z * w010 + f110.z * w110
              + f001.z * w001 + f101.z * w101 + f011.z * w011 + f111.z * w111;
        acc.w = f000.w * w000 + f100.w * w100 + f010.w * w010 + f110.w * w110
              + f001.w * w001 + f101.w * w101 + f011.w * w011 + f111.w * w111;

        *reinterpret_cast<float4*>(&sbuf[w][lane][L * 4]) = acc;
    }

    __syncwarp();

    const unsigned fullmask = 0xffffffffu;
    unsigned m = __ballot_sync(fullmask, active);
    bool warp_full = (m == 0xffffffffu);

    if (warp_full) {
#pragma unroll
        for (int it = 0; it < 7; ++it) {
            int f  = it * 30 + lane;
            int fc = f < 192 ? f : 191;          // clamp for uniform shfl
            int r  = fc / 6;
            int L  = fc - r * 6;
            float4 v = *reinterpret_cast<float4*>(&sbuf[w][r][L * 4]);
            uint32_t org_r = __shfl_sync(fullmask, orig, r);
            if (lane < 30 && f < 192)
                stcs_f4(&out[(size_t)org_r * 6 + L], v);
        }
    } else if (active) {
        float4* orow = out + (size_t)orig * 6;
#pragma unroll
        for (int L = 0; L < N_LEVELS; ++L)
            stcs_f4(&orow[L], *reinterpret_cast<float4*>(&sbuf[w][lane][L * 4]));
    }
}

// ---------------------------------------------------------------- launch
extern "C" void kernel_launch(void* const* d_in, const int* in_sizes, int n_in,
                              void* d_out, int out_size)
{
    const float* view_dirs   = (const float*)d_in[0];
    const float* ray_origins = (const float*)d_in[1];
    const float* table       = (const float*)d_in[2];
    float4* out              = (float4*)d_out;

    int n = in_sizes[0] / 3;
    int threads = 256;
    int blocks  = (n + threads - 1) / threads;

    k0_zero<<<NBINS / 4 / 256, 256>>>();
    k1_bin<<<blocks, threads>>>(view_dirs, ray_origins, n);
    k2a_scan<<<SCAN_BLOCKS, 1024>>>();
    k2b_scan<<<1, 1024>>>();
    k3_scatter<<<blocks, threads>>>(n);
    k4_encode<<<blocks, threads>>>(table, out, n);
}